// round 17
// baseline (speedup 1.0000x reference)
#include <cuda_runtime.h>
#include <stdint.h>

#define B_DIM 128
#define C_DIM 2048
#define HW 196
#define NC 8
#define NM 4
#define PART_N (B_DIM * HW)        // 25088
#define SLABS 8
#define CSLAB (C_DIM / SLABS)      // 256
#define PXT 4                      // pixels per thread
#define K1_THREADS 128
#define PXB (K1_THREADS * PXT)     // 512 pixels per block
#define NBX (PART_N / PXB)         // 49 pixel-blocks
#define NGRP 64                    // 32-channel groups for pass 2

// ---- scratch (__device__ globals; no allocation allowed) ----
__device__ float g_part[SLABS * NC * PART_N];        // A slab partials, 6.4 MB
__device__ float g_zpart[SLABS * NBX * 4 * NC];      // Z partials (slab,bx,seg,k)
__device__ float g_ypart[B_DIM * NGRP * NC];         // output partials from pass 2

// ---------------- packed f32x2 helpers (verified rounds 2-16) --------------
__device__ __forceinline__ unsigned long long fma2(
    unsigned long long a, unsigned long long b, unsigned long long c) {
    unsigned long long d;
    asm("fma.rn.f32x2 %0, %1, %2, %3;" : "=l"(d) : "l"(a), "l"(b), "l"(c));
    return d;
}
__device__ __forceinline__ unsigned long long dup2(float v) {
    unsigned long long d;
    asm("mov.b64 %0, {%1, %2};" : "=l"(d) : "f"(v), "f"(v));
    return d;
}
__device__ __forceinline__ void unpack2(unsigned long long v, float& lo, float& hi) {
    asm("mov.b64 {%0, %1}, %2;" : "=f"(lo), "=f"(hi) : "l"(v));
}

// ============================================================================
// K1: pass 1 over x — A maps + Z scalar only (Y moved to pass 2).
// grid (49, 8), 128 threads, 4 blocks/SM. Thread owns 4 adjacent pixels
// (float4 LDG). Per channel: A[k] += w_eff[k]*x (16 FMA2);
// zacc[k] += w_lo[k]*(4-px sum) (4 FMA2 + 3 FADD).
// ============================================================================
__global__ void __launch_bounds__(K1_THREADS, 4) k1_main(
    const float* __restrict__ x,
    const float* __restrict__ w_down,
    const float* __restrict__ w_cls) {
    __shared__ float wsh[CSLAB * 16];     // [c][0..7 A | 8..15 Z]  (16 KB)
    __shared__ float zsm[K1_THREADS][NC];

    const int bx = blockIdx.x;
    const int slab = blockIdx.y;
    const int t = threadIdx.x;

    // ---- inline weight prep ----
#pragma unroll
    for (int cl = t; cl < CSLAB; cl += K1_THREADS) {
        const int cg = slab * CSLAB + cl;
        float* w = &wsh[cl * 16];
#pragma unroll
        for (int k = 0; k < NC; ++k) {
            float s0 = w_down[(k * NM + 0) * C_DIM + cg];
            float s1 = w_down[(k * NM + 1) * C_DIM + cg];
            float s2 = w_down[(k * NM + 2) * C_DIM + cg];
            float s3 = w_down[(k * NM + 3) * C_DIM + cg];
            w[k]     = 0.25f * ((s0 + s1) + (s2 + s3));   // A (w_eff)
            w[8 + k] = w_cls[k * 2 * C_DIM + cg];         // Z (w_lo)
        }
    }
    __syncthreads();

    const int g0 = bx * PXB + PXT * t;   // 4 pixels, one batch (4 | 196)
    const int b = g0 / HW;
    const int p = g0 - b * HW;

    unsigned long long accA[16], zacc[4];
#pragma unroll
    for (int j = 0; j < 16; ++j) accA[j] = dup2(0.f);
#pragma unroll
    for (int j = 0; j < 4; ++j) zacc[j] = dup2(0.f);

    const float* xp = x + ((size_t)b * C_DIM + slab * CSLAB) * HW + p;

#pragma unroll 2
    for (int c0 = 0; c0 < CSLAB; c0 += 4) {
        float4 xv[4];
#pragma unroll
        for (int u = 0; u < 4; ++u)
            xv[u] = *(const float4*)&xp[(c0 + u) * HW];
#pragma unroll
        for (int u = 0; u < 4; ++u) {
            const float4 v = xv[u];
            unsigned long long xx[PXT];
            xx[0] = dup2(v.x); xx[1] = dup2(v.y);
            xx[2] = dup2(v.z); xx[3] = dup2(v.w);
            const ulonglong2* w = (const ulonglong2*)&wsh[(c0 + u) * 16];
            ulonglong2 wa0 = w[0], wa1 = w[1];       // A pairs
            ulonglong2 wz0 = w[2], wz1 = w[3];       // Z pairs
#pragma unroll
            for (int px = 0; px < PXT; ++px) {
                accA[0 * PXT + px] = fma2(xx[px], wa0.x, accA[0 * PXT + px]);
                accA[1 * PXT + px] = fma2(xx[px], wa0.y, accA[1 * PXT + px]);
                accA[2 * PXT + px] = fma2(xx[px], wa1.x, accA[2 * PXT + px]);
                accA[3 * PXT + px] = fma2(xx[px], wa1.y, accA[3 * PXT + px]);
            }
            float sx = (v.x + v.y) + (v.z + v.w);
            unsigned long long sxx = dup2(sx);
            zacc[0] = fma2(sxx, wz0.x, zacc[0]);
            zacc[1] = fma2(sxx, wz0.y, zacc[1]);
            zacc[2] = fma2(sxx, wz1.x, zacc[2]);
            zacc[3] = fma2(sxx, wz1.y, zacc[3]);
        }
    }

    // ---- write A per-pixel partials (float4, verified) ----
    float* base = &g_part[(size_t)slab * NC * PART_N + g0];
#pragma unroll
    for (int j = 0; j < 4; ++j) {
        float lo[PXT], hi[PXT];
#pragma unroll
        for (int px = 0; px < PXT; ++px) unpack2(accA[j * PXT + px], lo[px], hi[px]);
        *(float4*)&base[(2 * j) * PART_N]     = make_float4(lo[0], lo[1], lo[2], lo[3]);
        *(float4*)&base[(2 * j + 1) * PART_N] = make_float4(hi[0], hi[1], hi[2], hi[3]);
    }

    // ---- Z: segmented block reduction by batch (verified rounds 15/16) ----
#pragma unroll
    for (int j = 0; j < 4; ++j) {
        float lo, hi;
        unpack2(zacc[j], lo, hi);
        zsm[t][2 * j] = lo;
        zsm[t][2 * j + 1] = hi;
    }
    __syncthreads();
    if (t < 32) {
        const int seg = t >> 3, k = t & 7;
        const int btgt = (bx * PXB) / HW + seg;
        float s = 0.f;
#pragma unroll 1
        for (int u = 0; u < K1_THREADS; ++u) {
            const int bu = (bx * PXB + PXT * u) / HW;
            if (bu == btgt) s += zsm[u][k];
        }
        g_zpart[(((size_t)slab * NBX + bx) * 4 + seg) * NC + k] = s;
    }
}

// ============================================================================
// K2a: per (k, b): m_c[b,k,p] = sum_s A_part + beff[k] -> out_mc;
//      v[b,k] = mean_p m_c -> out_v.  grid (8, 128) x 224.
// ============================================================================
__global__ void __launch_bounds__(224) k2a(
    const float* __restrict__ b_down,
    float* __restrict__ out_v,
    float* __restrict__ out_mc) {
    __shared__ float wpart[7];
    const int k = blockIdx.x, b = blockIdx.y, t = threadIdx.x;
    const int g0 = b * HW;

    float mc = 0.f;
    if (t < HW) {
        float a[SLABS];
#pragma unroll
        for (int s = 0; s < SLABS; ++s)
            a[s] = g_part[((size_t)s * NC + k) * PART_N + g0 + t];
        float sum = ((a[0] + a[1]) + (a[2] + a[3])) +
                    ((a[4] + a[5]) + (a[6] + a[7]));
        float beff = 0.25f * ((b_down[4 * k] + b_down[4 * k + 1]) +
                              (b_down[4 * k + 2] + b_down[4 * k + 3]));
        mc = sum + beff;
        out_mc[((size_t)b * NC + k) * HW + t] = mc;
    }
    float s = mc;
#pragma unroll
    for (int o = 16; o; o >>= 1) s += __shfl_down_sync(0xffffffffu, s, o);
    const int lane = t & 31, warp = t >> 5;
    if (lane == 0) wpart[warp] = s;
    __syncthreads();
    if (t == 0) {
        float tot = 0.f;
#pragma unroll
        for (int w = 0; w < 7; ++w) tot += wpart[w];
        out_v[b * NC + k] = tot * (1.0f / (float)HW);
    }
}

// ============================================================================
// K2b: m[b,p] = (1/NC) sum_k v[b,k]*m_c[b,k,p].  grid 128 x 224.
// ============================================================================
__global__ void __launch_bounds__(224) k2b(
    const float* __restrict__ v_in,
    const float* __restrict__ mc_in,
    float* __restrict__ out_m) {
    __shared__ float vsh[NC];
    const int b = blockIdx.x, t = threadIdx.x;
    if (t < NC) vsh[t] = v_in[b * NC + t];
    __syncthreads();
    if (t < HW) {
        float a[NC];
#pragma unroll
        for (int k = 0; k < NC; ++k)
            a[k] = mc_in[((size_t)b * NC + k) * HW + t];
        float m = 0.f;
#pragma unroll
        for (int k = 0; k < NC; ++k) m = fmaf(vsh[k], a[k], m);
        out_m[b * HW + t] = m * (1.0f / (float)NC);
    }
}

// ============================================================================
// K3: pass 2 over x (round-6 verified structure, s1 dropped).
// grid (NGRP=64, B=128), 256 threads (8 warps). Warp w owns 4 channels;
// all 8 row-LDG.128s front-loaded. Per channel: gu = sum_p m[p]*x (raw,
// no /HW), then warp w (=class k) folds the block's 32 channels:
//   ypart[b,grp,k] = sum_c w_hi[k,c] * gu[c].
// ============================================================================
__global__ void __launch_bounds__(256) k3_gap(
    const float* __restrict__ x,
    const float* __restrict__ m_in,
    const float* __restrict__ w_cls) {
    __shared__ float4 msh4[49];
    __shared__ float gus[32];

    const int b = blockIdx.y;
    const int grp = blockIdx.x;
    const int t = threadIdx.x;
    const int w = t >> 5, l = t & 31;

    if (t < 49) msh4[t] = ((const float4*)(m_in + b * HW))[t];
    __syncthreads();

    const int cbase = grp * 32 + w * 4;
    const float* rowb = x + ((size_t)b * C_DIM + cbase) * HW;
    const bool tail = (l < 17);

    float4 xa[4], xb[4];
#pragma unroll
    for (int i = 0; i < 4; ++i)
        xa[i] = ((const float4*)(rowb + i * HW))[l];
#pragma unroll
    for (int i = 0; i < 4; ++i)
        xb[i] = tail ? ((const float4*)(rowb + i * HW))[l + 32]
                     : make_float4(0.f, 0.f, 0.f, 0.f);

    float4 ma = msh4[l];
    float4 mb = tail ? msh4[l + 32] : make_float4(0.f, 0.f, 0.f, 0.f);

#pragma unroll
    for (int i = 0; i < 4; ++i) {
        float s2 = fmaf(xa[i].x, ma.x, fmaf(xa[i].y, ma.y,
                   fmaf(xa[i].z, ma.z, xa[i].w * ma.w)));
        s2 = fmaf(xb[i].x, mb.x, fmaf(xb[i].y, mb.y,
             fmaf(xb[i].z, mb.z, fmaf(xb[i].w, mb.w, s2))));
#pragma unroll
        for (int o = 16; o; o >>= 1)
            s2 += __shfl_xor_sync(0xffffffffu, s2, o);
        if (l == 0) gus[w * 4 + i] = s2;
    }
    __syncthreads();

    // output partial: warp w = class k; lane l = local channel (raw gu)
    {
        const int c = grp * 32 + l;
        float val = w_cls[w * 2 * C_DIM + C_DIM + c] * gus[l];
#pragma unroll
        for (int o = 16; o; o >>= 1)
            val += __shfl_down_sync(0xffffffffu, val, o);
        if (l == 0)
            g_ypart[((size_t)b * NGRP + grp) * NC + w] = val;
    }
}

// ============================================================================
// K4: output[b,k] = (1/HW)(sum_grp ypart + sum Z) + b_cls[k].
// grid 128 x 256: warp w = class k, lanes cover 64 groups (2 each).
// ============================================================================
__global__ void __launch_bounds__(256) k4_out(
    const float* __restrict__ b_cls,
    float* __restrict__ out_output) {
    const int b = blockIdx.x;
    const int t = threadIdx.x;
    const int w = t >> 5, l = t & 31;

    float v = g_ypart[((size_t)b * NGRP + l) * NC + w] +
              g_ypart[((size_t)b * NGRP + l + 32) * NC + w];
#pragma unroll
    for (int o = 16; o; o >>= 1)
        v += __shfl_down_sync(0xffffffffu, v, o);
    if (l == 0) {
        // Z contribution: batch b's pixels live in <=2 pixel-blocks
        const int bx_lo = (b * HW) / PXB;
        const int bx_hi = (b * HW + HW - 1) / PXB;
        float z = 0.f;
        for (int bxx = bx_lo; bxx <= bx_hi; ++bxx) {
            const int seg = b - (bxx * PXB) / HW;
#pragma unroll
            for (int sl = 0; sl < SLABS; ++sl)
                z += g_zpart[(((size_t)sl * NBX + bxx) * 4 + seg) * NC + w];
        }
        out_output[b * NC + w] = (v + z) * (1.0f / (float)HW) + b_cls[w];
    }
}

// ============================================================================
// kernel_launch: 5 launches, graph-capturable, deterministic.
// Output layout: v[128,8]@0, output[128,8]@1024, m[128,196]@2048,
//                m_c[128,8,196]@27136.
// ============================================================================
extern "C" void kernel_launch(void* const* d_in, const int* in_sizes, int n_in,
                              void* d_out, int out_size) {
    const float* x      = (const float*)d_in[0];
    const float* w_down = (const float*)d_in[1];
    const float* b_down = (const float*)d_in[2];
    const float* w_cls  = (const float*)d_in[3];
    const float* b_cls  = (const float*)d_in[4];

    float* out        = (float*)d_out;
    float* out_v      = out;
    float* out_output = out + 1024;
    float* out_m      = out + 2048;
    float* out_mc     = out + 27136;

    k1_main<<<dim3(NBX, SLABS), K1_THREADS>>>(x, w_down, w_cls);
    k2a<<<dim3(NC, B_DIM), 224>>>(b_down, out_v, out_mc);
    k2b<<<B_DIM, 224>>>(out_v, out_mc, out_m);
    k3_gap<<<dim3(NGRP, B_DIM), 256>>>(x, out_m, w_cls);
    k4_out<<<B_DIM, 256>>>(b_cls, out_output);
}